// round 1
// baseline (speedup 1.0000x reference)
#include <cuda_runtime.h>

// Problem dims (fixed by the reference)
#define BATCH 8
#define SEQ   2048
#define DMODEL 1024
#define NROWS (BATCH * SEQ)          // 16384

// Scratch: q,k,v projections (64 MB each) + scores (128 MB)
__device__ float g_proj_q[(size_t)NROWS * DMODEL];
__device__ float g_proj_k[(size_t)NROWS * DMODEL];
__device__ float g_proj_v[(size_t)NROWS * DMODEL];
__device__ float g_scores[(size_t)BATCH * SEQ * SEQ];

// ---------------------------------------------------------------------------
// Kernel 1: projections. C[n,e] = sum_d A[n,d] * W[d,e] + b[e]
// A: [NROWS, DMODEL] row-major, W: [DMODEL, DMODEL] row-major.
// 128x128 tile, BK=8, 256 threads, 8x8 per-thread micro-tile.
// grid = (DMODEL/128, NROWS/128, 3); z selects Q/K/V.
// ---------------------------------------------------------------------------
__global__ __launch_bounds__(256) void proj_kernel(
    const float* __restrict__ Q, const float* __restrict__ K,
    const float* __restrict__ V,
    const float* __restrict__ Wq, const float* __restrict__ Wk,
    const float* __restrict__ Wv,
    const float* __restrict__ bq, const float* __restrict__ bk,
    const float* __restrict__ bv)
{
    const int which = blockIdx.z;
    const float* A    = (which == 0) ? Q  : (which == 1) ? K  : V;
    const float* W    = (which == 0) ? Wq : (which == 1) ? Wk : Wv;
    const float* bias = (which == 0) ? bq : (which == 1) ? bk : bv;
    float* C          = (which == 0) ? g_proj_q : (which == 1) ? g_proj_k : g_proj_v;

    __shared__ float As[8][128];
    __shared__ float Bs[8][128];

    const int m0 = blockIdx.y * 128;
    const int n0 = blockIdx.x * 128;
    const int t  = threadIdx.x;
    const int tx = t & 15;        // 0..15 -> output col group
    const int ty = t >> 4;        // 0..15 -> output row group

    // A-tile load indices: 128 rows x 8 k, float4 along k
    const int arow = t >> 1;
    const int ak4  = (t & 1) * 4;
    // W-tile load indices: 8 k-rows x 128 n, float4 along n
    const int brow = t >> 5;
    const int bn4  = (t & 31) * 4;

    float acc[8][8];
    #pragma unroll
    for (int i = 0; i < 8; i++)
        #pragma unroll
        for (int j = 0; j < 8; j++) acc[i][j] = 0.f;

    for (int k0 = 0; k0 < DMODEL; k0 += 8) {
        float4 a = *(const float4*)&A[(size_t)(m0 + arow) * DMODEL + k0 + ak4];
        As[ak4 + 0][arow] = a.x;
        As[ak4 + 1][arow] = a.y;
        As[ak4 + 2][arow] = a.z;
        As[ak4 + 3][arow] = a.w;
        float4 w4 = *(const float4*)&W[(size_t)(k0 + brow) * DMODEL + n0 + bn4];
        *(float4*)&Bs[brow][bn4] = w4;
        __syncthreads();

        #pragma unroll
        for (int kk = 0; kk < 8; kk++) {
            float4 a0 = *(const float4*)&As[kk][ty * 8];
            float4 a1 = *(const float4*)&As[kk][ty * 8 + 4];
            float4 b0 = *(const float4*)&Bs[kk][tx * 8];
            float4 b1 = *(const float4*)&Bs[kk][tx * 8 + 4];
            float ra[8] = {a0.x, a0.y, a0.z, a0.w, a1.x, a1.y, a1.z, a1.w};
            float rb[8] = {b0.x, b0.y, b0.z, b0.w, b1.x, b1.y, b1.z, b1.w};
            #pragma unroll
            for (int i = 0; i < 8; i++)
                #pragma unroll
                for (int j = 0; j < 8; j++)
                    acc[i][j] += ra[i] * rb[j];
        }
        __syncthreads();
    }

    #pragma unroll
    for (int i = 0; i < 8; i++) {
        const int row = m0 + ty * 8 + i;
        float* crow = &C[(size_t)row * DMODEL + n0];
        #pragma unroll
        for (int j = 0; j < 8; j++)
            crow[tx * 8 + j] = acc[i][j] + bias[n0 + tx * 8 + j];
    }
}

// ---------------------------------------------------------------------------
// Kernel 2: scores[b,i,j] = q[b,i,:]·k[b,j,:] / 32 for j<=i; -1e9 on the
// masked part of diagonal tiles. Upper tiles are skipped entirely (never read).
// NT GEMM: A = q [SEQ, D] rm, B = k [SEQ, D] rm, C = A·B^T.
// grid = (SEQ/128 jt, SEQ/128 it, BATCH)
// ---------------------------------------------------------------------------
__global__ __launch_bounds__(256) void scores_kernel()
{
    const int jt = blockIdx.x, it = blockIdx.y, b = blockIdx.z;
    if (jt > it) return;  // strictly-upper tile: fully masked

    const float* q = g_proj_q + (size_t)b * SEQ * DMODEL;
    const float* k = g_proj_k + (size_t)b * SEQ * DMODEL;
    float* sc      = g_scores + (size_t)b * SEQ * SEQ;

    const int i0 = it * 128;
    const int j0 = jt * 128;

    __shared__ float As[8][128];
    __shared__ float Bs[8][128];

    const int t  = threadIdx.x;
    const int tx = t & 15;
    const int ty = t >> 4;
    const int arow = t >> 1;
    const int ak4  = (t & 1) * 4;

    float acc[8][8];
    #pragma unroll
    for (int i = 0; i < 8; i++)
        #pragma unroll
        for (int j = 0; j < 8; j++) acc[i][j] = 0.f;

    for (int c0 = 0; c0 < DMODEL; c0 += 8) {
        float4 a = *(const float4*)&q[(size_t)(i0 + arow) * DMODEL + c0 + ak4];
        As[ak4 + 0][arow] = a.x;
        As[ak4 + 1][arow] = a.y;
        As[ak4 + 2][arow] = a.z;
        As[ak4 + 3][arow] = a.w;
        float4 kb = *(const float4*)&k[(size_t)(j0 + arow) * DMODEL + c0 + ak4];
        Bs[ak4 + 0][arow] = kb.x;
        Bs[ak4 + 1][arow] = kb.y;
        Bs[ak4 + 2][arow] = kb.z;
        Bs[ak4 + 3][arow] = kb.w;
        __syncthreads();

        #pragma unroll
        for (int kk = 0; kk < 8; kk++) {
            float4 a0 = *(const float4*)&As[kk][ty * 8];
            float4 a1 = *(const float4*)&As[kk][ty * 8 + 4];
            float4 b0 = *(const float4*)&Bs[kk][tx * 8];
            float4 b1 = *(const float4*)&Bs[kk][tx * 8 + 4];
            float ra[8] = {a0.x, a0.y, a0.z, a0.w, a1.x, a1.y, a1.z, a1.w};
            float rb[8] = {b0.x, b0.y, b0.z, b0.w, b1.x, b1.y, b1.z, b1.w};
            #pragma unroll
            for (int i = 0; i < 8; i++)
                #pragma unroll
                for (int j = 0; j < 8; j++)
                    acc[i][j] += ra[i] * rb[j];
        }
        __syncthreads();
    }

    const float scale = 0.03125f;  // 1/sqrt(1024)
    #pragma unroll
    for (int i = 0; i < 8; i++) {
        const int gi = i0 + ty * 8 + i;
        float* srow = &sc[(size_t)gi * SEQ];
        #pragma unroll
        for (int j = 0; j < 8; j++) {
            const int gj = j0 + tx * 8 + j;
            srow[gj] = (gj <= gi) ? acc[i][j] * scale : -1e9f;
        }
    }
}

// ---------------------------------------------------------------------------
// Kernel 3: causal softmax in place. One CTA per row.
// Row (b,i): valid length = i+1. Writes weights; zeros for j > i.
// ---------------------------------------------------------------------------
__global__ __launch_bounds__(256) void softmax_kernel()
{
    const int r = blockIdx.x;              // 0..NROWS-1
    const int b = r / SEQ;
    const int i = r % SEQ;
    float* row = g_scores + (size_t)b * SEQ * SEQ + (size_t)i * SEQ;
    const int len = i + 1;
    const int t = threadIdx.x;

    __shared__ float red[256];

    float mx = -3.0e38f;
    for (int j = t; j < len; j += 256) mx = fmaxf(mx, row[j]);
    red[t] = mx;
    __syncthreads();
    for (int s2 = 128; s2 > 0; s2 >>= 1) {
        if (t < s2) red[t] = fmaxf(red[t], red[t + s2]);
        __syncthreads();
    }
    mx = red[0];
    __syncthreads();

    float sum = 0.f;
    for (int j = t; j < len; j += 256) sum += __expf(row[j] - mx);
    red[t] = sum;
    __syncthreads();
    for (int s2 = 128; s2 > 0; s2 >>= 1) {
        if (t < s2) red[t] += red[t + s2];
        __syncthreads();
    }
    const float inv = 1.0f / red[0];

    for (int j = t; j < SEQ; j += 256)
        row[j] = (j < len) ? __expf(row[j] - mx) * inv : 0.f;
}

// ---------------------------------------------------------------------------
// Kernel 4: out[b,i,e] = sum_j weights[b,i,j] * v[b,j,e]
// NN GEMM: A = weights [SEQ,SEQ] rm, B = v [SEQ,D] rm.
// Causal: weights are zero beyond j = i, so truncate K-loop at tile end.
// grid = (DMODEL/128, SEQ/128, BATCH)
// ---------------------------------------------------------------------------
__global__ __launch_bounds__(256) void out_kernel(float* __restrict__ Out)
{
    const int b  = blockIdx.z;
    const int it = blockIdx.y;
    const int nt = blockIdx.x;

    const float* Wt = g_scores + (size_t)b * SEQ * SEQ;
    const float* Vv = g_proj_v + (size_t)b * SEQ * DMODEL;
    float* C        = Out + (size_t)b * SEQ * DMODEL;

    const int m0 = it * 128;
    const int n0 = nt * 128;
    const int kmax = m0 + 128;   // rows in this tile have i < m0+128

    __shared__ float As[8][128];
    __shared__ float Bs[8][128];

    const int t  = threadIdx.x;
    const int tx = t & 15;
    const int ty = t >> 4;
    const int arow = t >> 1;
    const int ak4  = (t & 1) * 4;
    const int brow = t >> 5;
    const int bn4  = (t & 31) * 4;

    float acc[8][8];
    #pragma unroll
    for (int i = 0; i < 8; i++)
        #pragma unroll
        for (int j = 0; j < 8; j++) acc[i][j] = 0.f;

    for (int k0 = 0; k0 < kmax; k0 += 8) {
        float4 a = *(const float4*)&Wt[(size_t)(m0 + arow) * SEQ + k0 + ak4];
        As[ak4 + 0][arow] = a.x;
        As[ak4 + 1][arow] = a.y;
        As[ak4 + 2][arow] = a.z;
        As[ak4 + 3][arow] = a.w;
        float4 v4 = *(const float4*)&Vv[(size_t)(k0 + brow) * DMODEL + n0 + bn4];
        *(float4*)&Bs[brow][bn4] = v4;
        __syncthreads();

        #pragma unroll
        for (int kk = 0; kk < 8; kk++) {
            float4 a0 = *(const float4*)&As[kk][ty * 8];
            float4 a1 = *(const float4*)&As[kk][ty * 8 + 4];
            float4 b0 = *(const float4*)&Bs[kk][tx * 8];
            float4 b1 = *(const float4*)&Bs[kk][tx * 8 + 4];
            float ra[8] = {a0.x, a0.y, a0.z, a0.w, a1.x, a1.y, a1.z, a1.w};
            float rb[8] = {b0.x, b0.y, b0.z, b0.w, b1.x, b1.y, b1.z, b1.w};
            #pragma unroll
            for (int i = 0; i < 8; i++)
                #pragma unroll
                for (int j = 0; j < 8; j++)
                    acc[i][j] += ra[i] * rb[j];
        }
        __syncthreads();
    }

    #pragma unroll
    for (int i = 0; i < 8; i++) {
        const int row = m0 + ty * 8 + i;
        float* crow = &C[(size_t)row * DMODEL + n0];
        #pragma unroll
        for (int j = 0; j < 8; j++)
            crow[tx * 8 + j] = acc[i][j];
    }
}

// ---------------------------------------------------------------------------
// Launch. Inputs (metadata order): Q, K, V, Wq, Wk, Wv, bq, bk, bv, mask.
// mask is exactly tril(ones) -> causality is implemented directly.
// ---------------------------------------------------------------------------
extern "C" void kernel_launch(void* const* d_in, const int* in_sizes, int n_in,
                              void* d_out, int out_size)
{
    const float* Q  = (const float*)d_in[0];
    const float* K  = (const float*)d_in[1];
    const float* V  = (const float*)d_in[2];
    const float* Wq = (const float*)d_in[3];
    const float* Wk = (const float*)d_in[4];
    const float* Wv = (const float*)d_in[5];
    const float* bq = (const float*)d_in[6];
    const float* bk = (const float*)d_in[7];
    const float* bv = (const float*)d_in[8];
    float* Out = (float*)d_out;

    proj_kernel<<<dim3(DMODEL / 128, NROWS / 128, 3), 256>>>(
        Q, K, V, Wq, Wk, Wv, bq, bk, bv);
    scores_kernel<<<dim3(SEQ / 128, SEQ / 128, BATCH), 256>>>();
    softmax_kernel<<<NROWS, 256>>>();
    out_kernel<<<dim3(DMODEL / 128, SEQ / 128, BATCH), 256>>>(Out);
}

// round 2
// speedup vs baseline: 3.5176x; 3.5176x over previous
#include <cuda_runtime.h>
#include <cstdint>

// Problem dims (fixed by the reference)
#define BATCH 8
#define SEQ   2048
#define DMODEL 1024
#define NROWS (BATCH * SEQ)          // 16384

// Scratch: q,k,v projections (64 MB each) + scores (128 MB)
__device__ float g_proj_q[(size_t)NROWS * DMODEL];
__device__ float g_proj_k[(size_t)NROWS * DMODEL];
__device__ float g_proj_v[(size_t)NROWS * DMODEL];
__device__ float g_scores[(size_t)BATCH * SEQ * SEQ];

// ---------------------------------------------------------------------------
// Helpers: tf32 cvt, mma.sync m16n8k8, cp.async
// ---------------------------------------------------------------------------
__device__ __forceinline__ uint32_t cvt_tf32(float x) {
    uint32_t r;
    asm("cvt.rna.tf32.f32 %0, %1;" : "=r"(r) : "f"(x));
    return r;
}

__device__ __forceinline__ void mma8(float* c,
                                     uint32_t a0, uint32_t a1, uint32_t a2, uint32_t a3,
                                     uint32_t b0, uint32_t b1) {
    asm volatile(
        "mma.sync.aligned.m16n8k8.row.col.f32.tf32.tf32.f32 "
        "{%0,%1,%2,%3},{%4,%5,%6,%7},{%8,%9},{%0,%1,%2,%3};\n"
        : "+f"(c[0]), "+f"(c[1]), "+f"(c[2]), "+f"(c[3])
        : "r"(a0), "r"(a1), "r"(a2), "r"(a3), "r"(b0), "r"(b1));
}

__device__ __forceinline__ void cpa16(uint32_t saddr, const void* g) {
    asm volatile("cp.async.cg.shared.global [%0], [%1], 16;\n" :: "r"(saddr), "l"(g));
}
#define CPA_COMMIT()  asm volatile("cp.async.commit_group;\n")
#define CPA_WAIT1()   asm volatile("cp.async.wait_group 1;\n" ::: "memory")
#define CPA_WAIT0()   asm volatile("cp.async.wait_group 0;\n" ::: "memory")

// SMEM layout (u32 indices), 2 stages each.
// A tile:   [128][36]  (m-major, stride 36 -> conflict-free frags & stores)
// B tile:   [32][136]  (k-major, stride 136) for proj/out (B row-major source)
// B tile T: [128][36]  (j-major, stride 36)  for scores (K rows, frag read transposed)
#define AS_STRIDE 36
#define AS_U32    (128 * AS_STRIDE)       // 4608
#define BS_STRIDE 136
#define BS_U32    (32 * BS_STRIDE)        // 4352
#define SMEM_PROJ_BYTES ((2 * AS_U32 + 2 * BS_U32) * 4)   // 71680
#define SMEM_SCOR_BYTES ((2 * AS_U32 + 2 * AS_U32) * 4)   // 73728

// ---------------------------------------------------------------------------
// Kernel 1: projections. C[n,e] = sum_d A[n,d]*W[d,e] + b[e]
// grid = (DMODEL/128, NROWS/128, 3)
// ---------------------------------------------------------------------------
__global__ __launch_bounds__(256, 2) void proj_kernel(
    const float* __restrict__ Q, const float* __restrict__ K,
    const float* __restrict__ V,
    const float* __restrict__ Wq, const float* __restrict__ Wk,
    const float* __restrict__ Wv,
    const float* __restrict__ bq, const float* __restrict__ bk,
    const float* __restrict__ bv)
{
    const int which = blockIdx.z;
    const float* A    = (which == 0) ? Q  : (which == 1) ? K  : V;
    const float* W    = (which == 0) ? Wq : (which == 1) ? Wk : Wv;
    const float* bias = (which == 0) ? bq : (which == 1) ? bk : bv;
    float* C          = (which == 0) ? g_proj_q : (which == 1) ? g_proj_k : g_proj_v;

    extern __shared__ uint32_t sm[];
    const uint32_t smb = (uint32_t)__cvta_generic_to_shared(sm);

    const int m0 = blockIdx.y * 128;
    const int n0 = blockIdx.x * 128;
    const int t  = threadIdx.x;
    const int warp = t >> 5, lane = t & 31;
    const int wm = warp >> 2, wn = warp & 3;      // 2 x 4 warp grid
    const int g  = lane >> 2, tq = lane & 3;

    // cp.async per-thread addressing (4 chunks of 16B each for A and B)
    const int a_row = t >> 3,        a_c4 = (t & 7)  * 4;   // + 32 rows per chunk
    const int b_row = t >> 5,        b_c4 = (t & 31) * 4;   // + 8 k-rows per chunk

    float acc[4][4][4];
    #pragma unroll
    for (int i = 0; i < 4; i++)
        #pragma unroll
        for (int j = 0; j < 4; j++)
            #pragma unroll
            for (int c = 0; c < 4; c++) acc[i][j][c] = 0.f;

    const int T = DMODEL / 32;

    // stage issue: tile k0 = tt*32 into buffer s
    auto issue = [&](int tt, int s) {
        const int k0 = tt * 32;
        #pragma unroll
        for (int i = 0; i < 4; i++) {
            const int r = a_row + i * 32;
            cpa16(smb + (s * AS_U32 + r * AS_STRIDE + a_c4) * 4,
                  &A[(size_t)(m0 + r) * DMODEL + k0 + a_c4]);
        }
        #pragma unroll
        for (int i = 0; i < 4; i++) {
            const int r = b_row + i * 8;
            cpa16(smb + (2 * AS_U32 + s * BS_U32 + r * BS_STRIDE + b_c4) * 4,
                  &W[(size_t)(k0 + r) * DMODEL + n0 + b_c4]);
        }
    };

    issue(0, 0);
    CPA_COMMIT();

    for (int tt = 0; tt < T; tt++) {
        const int cur = tt & 1;
        if (tt + 1 < T) { issue(tt + 1, cur ^ 1); CPA_COMMIT(); CPA_WAIT1(); }
        else           { CPA_WAIT0(); }
        __syncthreads();

        const uint32_t* As = sm + cur * AS_U32;
        const uint32_t* Bs = sm + 2 * AS_U32 + cur * BS_U32;

        #pragma unroll
        for (int ks = 0; ks < 4; ks++) {
            const int kb = ks * 8;
            uint32_t af[4][4], bf[4][2];
            #pragma unroll
            for (int mt = 0; mt < 4; mt++) {
                const int r0 = wm * 64 + mt * 16 + g;
                af[mt][0] = cvt_tf32(__uint_as_float(As[(r0)     * AS_STRIDE + kb + tq]));
                af[mt][1] = cvt_tf32(__uint_as_float(As[(r0 + 8) * AS_STRIDE + kb + tq]));
                af[mt][2] = cvt_tf32(__uint_as_float(As[(r0)     * AS_STRIDE + kb + tq + 4]));
                af[mt][3] = cvt_tf32(__uint_as_float(As[(r0 + 8) * AS_STRIDE + kb + tq + 4]));
            }
            #pragma unroll
            for (int nt = 0; nt < 4; nt++) {
                const int c0 = wn * 32 + nt * 8 + g;
                bf[nt][0] = cvt_tf32(__uint_as_float(Bs[(kb + tq)     * BS_STRIDE + c0]));
                bf[nt][1] = cvt_tf32(__uint_as_float(Bs[(kb + tq + 4) * BS_STRIDE + c0]));
            }
            #pragma unroll
            for (int mt = 0; mt < 4; mt++)
                #pragma unroll
                for (int nt = 0; nt < 4; nt++)
                    mma8(acc[mt][nt], af[mt][0], af[mt][1], af[mt][2], af[mt][3],
                         bf[nt][0], bf[nt][1]);
        }
        __syncthreads();
    }

    // Epilogue: C = acc + bias
    #pragma unroll
    for (int mt = 0; mt < 4; mt++) {
        const int r0 = m0 + wm * 64 + mt * 16 + g;
        #pragma unroll
        for (int nt = 0; nt < 4; nt++) {
            const int c0 = n0 + wn * 32 + nt * 8 + tq * 2;
            const float b0 = bias[c0], b1 = bias[c0 + 1];
            float* p0 = &C[(size_t)r0 * DMODEL + c0];
            float* p1 = &C[(size_t)(r0 + 8) * DMODEL + c0];
            p0[0] = acc[mt][nt][0] + b0;  p0[1] = acc[mt][nt][1] + b1;
            p1[0] = acc[mt][nt][2] + b0;  p1[1] = acc[mt][nt][3] + b1;
        }
    }
}

// ---------------------------------------------------------------------------
// Kernel 2: scores[b,i,j] = q[b,i,:]·k[b,j,:]/32 (j<=i), -1e9 above diagonal
// in diagonal tiles; strictly-upper tiles skipped. C = q·kT (NT GEMM).
// grid = (SEQ/128 jt, SEQ/128 it, BATCH)
// ---------------------------------------------------------------------------
__global__ __launch_bounds__(256, 2) void scores_kernel()
{
    const int jt = blockIdx.x, it = blockIdx.y, b = blockIdx.z;
    if (jt > it) return;

    const float* q = g_proj_q + (size_t)b * SEQ * DMODEL;
    const float* k = g_proj_k + (size_t)b * SEQ * DMODEL;
    float* sc      = g_scores + (size_t)b * SEQ * SEQ;

    extern __shared__ uint32_t sm[];
    const uint32_t smb = (uint32_t)__cvta_generic_to_shared(sm);

    const int i0 = it * 128, j0 = jt * 128;
    const int t  = threadIdx.x;
    const int warp = t >> 5, lane = t & 31;
    const int wm = warp >> 2, wn = warp & 3;
    const int g  = lane >> 2, tq = lane & 3;

    const int a_row = t >> 3, a_c4 = (t & 7) * 4;

    float acc[4][4][4];
    #pragma unroll
    for (int i = 0; i < 4; i++)
        #pragma unroll
        for (int j = 0; j < 4; j++)
            #pragma unroll
            for (int c = 0; c < 4; c++) acc[i][j][c] = 0.f;

    const int T = DMODEL / 32;

    auto issue = [&](int tt, int s) {
        const int k0 = tt * 32;
        #pragma unroll
        for (int i = 0; i < 4; i++) {
            const int r = a_row + i * 32;
            cpa16(smb + (s * AS_U32 + r * AS_STRIDE + a_c4) * 4,
                  &q[(size_t)(i0 + r) * DMODEL + k0 + a_c4]);
            cpa16(smb + ((2 + s) * AS_U32 + r * AS_STRIDE + a_c4) * 4,
                  &k[(size_t)(j0 + r) * DMODEL + k0 + a_c4]);
        }
    };

    issue(0, 0);
    CPA_COMMIT();

    for (int tt = 0; tt < T; tt++) {
        const int cur = tt & 1;
        if (tt + 1 < T) { issue(tt + 1, cur ^ 1); CPA_COMMIT(); CPA_WAIT1(); }
        else           { CPA_WAIT0(); }
        __syncthreads();

        const uint32_t* As = sm + cur * AS_U32;
        const uint32_t* Bs = sm + (2 + cur) * AS_U32;   // K rows, [j][d] layout

        #pragma unroll
        for (int ks = 0; ks < 4; ks++) {
            const int kb = ks * 8;
            uint32_t af[4][4], bf[4][2];
            #pragma unroll
            for (int mt = 0; mt < 4; mt++) {
                const int r0 = wm * 64 + mt * 16 + g;
                af[mt][0] = cvt_tf32(__uint_as_float(As[(r0)     * AS_STRIDE + kb + tq]));
                af[mt][1] = cvt_tf32(__uint_as_float(As[(r0 + 8) * AS_STRIDE + kb + tq]));
                af[mt][2] = cvt_tf32(__uint_as_float(As[(r0)     * AS_STRIDE + kb + tq + 4]));
                af[mt][3] = cvt_tf32(__uint_as_float(As[(r0 + 8) * AS_STRIDE + kb + tq + 4]));
            }
            #pragma unroll
            for (int nt = 0; nt < 4; nt++) {
                const int c0 = wn * 32 + nt * 8 + g;     // j row in K tile
                bf[nt][0] = cvt_tf32(__uint_as_float(Bs[c0 * AS_STRIDE + kb + tq]));
                bf[nt][1] = cvt_tf32(__uint_as_float(Bs[c0 * AS_STRIDE + kb + tq + 4]));
            }
            #pragma unroll
            for (int mt = 0; mt < 4; mt++)
                #pragma unroll
                for (int nt = 0; nt < 4; nt++)
                    mma8(acc[mt][nt], af[mt][0], af[mt][1], af[mt][2], af[mt][3],
                         bf[nt][0], bf[nt][1]);
        }
        __syncthreads();
    }

    const float scale = 0.03125f;   // 1/sqrt(1024)
    #pragma unroll
    for (int mt = 0; mt < 4; mt++) {
        const int gi0 = i0 + wm * 64 + mt * 16 + g;
        #pragma unroll
        for (int nt = 0; nt < 4; nt++) {
            const int gj = j0 + wn * 32 + nt * 8 + tq * 2;
            float* p0 = &sc[(size_t)gi0 * SEQ + gj];
            float* p1 = &sc[(size_t)(gi0 + 8) * SEQ + gj];
            p0[0] = (gj     <= gi0)     ? acc[mt][nt][0] * scale : -1e9f;
            p0[1] = (gj + 1 <= gi0)     ? acc[mt][nt][1] * scale : -1e9f;
            p1[0] = (gj     <= gi0 + 8) ? acc[mt][nt][2] * scale : -1e9f;
            p1[1] = (gj + 1 <= gi0 + 8) ? acc[mt][nt][3] * scale : -1e9f;
        }
    }
}

// ---------------------------------------------------------------------------
// Kernel 3: causal softmax in place. One CTA per row; len = i+1; zeros beyond.
// ---------------------------------------------------------------------------
__global__ __launch_bounds__(256) void softmax_kernel()
{
    const int r = blockIdx.x;
    const int b = r / SEQ;
    const int i = r % SEQ;
    float* row = g_scores + (size_t)b * SEQ * SEQ + (size_t)i * SEQ;
    const int len = i + 1;
    const int t = threadIdx.x;

    __shared__ float red[256];

    float mx = -3.0e38f;
    for (int j = t; j < len; j += 256) mx = fmaxf(mx, row[j]);
    red[t] = mx;
    __syncthreads();
    for (int s2 = 128; s2 > 0; s2 >>= 1) {
        if (t < s2) red[t] = fmaxf(red[t], red[t + s2]);
        __syncthreads();
    }
    mx = red[0];
    __syncthreads();

    float sum = 0.f;
    for (int j = t; j < len; j += 256) sum += __expf(row[j] - mx);
    red[t] = sum;
    __syncthreads();
    for (int s2 = 128; s2 > 0; s2 >>= 1) {
        if (t < s2) red[t] += red[t + s2];
        __syncthreads();
    }
    const float inv = 1.0f / red[0];

    for (int j = t; j < SEQ; j += 256)
        row[j] = (j < len) ? __expf(row[j] - mx) * inv : 0.f;
}

// ---------------------------------------------------------------------------
// Kernel 4: out = weights · v  (NN GEMM, K-loop truncated at causal boundary)
// grid = (DMODEL/128, SEQ/128, BATCH)
// ---------------------------------------------------------------------------
__global__ __launch_bounds__(256, 2) void out_kernel(float* __restrict__ Out)
{
    const int b  = blockIdx.z;
    const int it = blockIdx.y;
    const int nt0 = blockIdx.x;

    const float* Wt = g_scores + (size_t)b * SEQ * SEQ;
    const float* Vv = g_proj_v + (size_t)b * SEQ * DMODEL;
    float* C        = Out + (size_t)b * SEQ * DMODEL;

    extern __shared__ uint32_t sm[];
    const uint32_t smb = (uint32_t)__cvta_generic_to_shared(sm);

    const int m0 = it * 128;
    const int n0 = nt0 * 128;
    const int t  = threadIdx.x;
    const int warp = t >> 5, lane = t & 31;
    const int wm = warp >> 2, wn = warp & 3;
    const int g  = lane >> 2, tq = lane & 3;

    const int a_row = t >> 3,  a_c4 = (t & 7)  * 4;
    const int b_row = t >> 5,  b_c4 = (t & 31) * 4;

    float acc[4][4][4];
    #pragma unroll
    for (int i = 0; i < 4; i++)
        #pragma unroll
        for (int j = 0; j < 4; j++)
            #pragma unroll
            for (int c = 0; c < 4; c++) acc[i][j][c] = 0.f;

    const int T = (it + 1) * 4;    // K-loop to causal tile boundary (kmax = m0+128)

    auto issue = [&](int tt, int s) {
        const int k0 = tt * 32;
        #pragma unroll
        for (int i = 0; i < 4; i++) {
            const int r = a_row + i * 32;
            cpa16(smb + (s * AS_U32 + r * AS_STRIDE + a_c4) * 4,
                  &Wt[(size_t)(m0 + r) * SEQ + k0 + a_c4]);
        }
        #pragma unroll
        for (int i = 0; i < 4; i++) {
            const int r = b_row + i * 8;
            cpa16(smb + (2 * AS_U32 + s * BS_U32 + r * BS_STRIDE + b_c4) * 4,
                  &Vv[(size_t)(k0 + r) * DMODEL + n0 + b_c4]);
        }
    };

    issue(0, 0);
    CPA_COMMIT();

    for (int tt = 0; tt < T; tt++) {
        const int cur = tt & 1;
        if (tt + 1 < T) { issue(tt + 1, cur ^ 1); CPA_COMMIT(); CPA_WAIT1(); }
        else           { CPA_WAIT0(); }
        __syncthreads();

        const uint32_t* As = sm + cur * AS_U32;
        const uint32_t* Bs = sm + 2 * AS_U32 + cur * BS_U32;

        #pragma unroll
        for (int ks = 0; ks < 4; ks++) {
            const int kb = ks * 8;
            uint32_t af[4][4], bf[4][2];
            #pragma unroll
            for (int mt = 0; mt < 4; mt++) {
                const int r0 = wm * 64 + mt * 16 + g;
                af[mt][0] = cvt_tf32(__uint_as_float(As[(r0)     * AS_STRIDE + kb + tq]));
                af[mt][1] = cvt_tf32(__uint_as_float(As[(r0 + 8) * AS_STRIDE + kb + tq]));
                af[mt][2] = cvt_tf32(__uint_as_float(As[(r0)     * AS_STRIDE + kb + tq + 4]));
                af[mt][3] = cvt_tf32(__uint_as_float(As[(r0 + 8) * AS_STRIDE + kb + tq + 4]));
            }
            #pragma unroll
            for (int nt = 0; nt < 4; nt++) {
                const int c0 = wn * 32 + nt * 8 + g;
                bf[nt][0] = cvt_tf32(__uint_as_float(Bs[(kb + tq)     * BS_STRIDE + c0]));
                bf[nt][1] = cvt_tf32(__uint_as_float(Bs[(kb + tq + 4) * BS_STRIDE + c0]));
            }
            #pragma unroll
            for (int mt = 0; mt < 4; mt++)
                #pragma unroll
                for (int nt = 0; nt < 4; nt++)
                    mma8(acc[mt][nt], af[mt][0], af[mt][1], af[mt][2], af[mt][3],
                         bf[nt][0], bf[nt][1]);
        }
        __syncthreads();
    }

    #pragma unroll
    for (int mt = 0; mt < 4; mt++) {
        const int r0 = m0 + wm * 64 + mt * 16 + g;
        #pragma unroll
        for (int nt = 0; nt < 4; nt++) {
            const int c0 = n0 + wn * 32 + nt * 8 + tq * 2;
            float* p0 = &C[(size_t)r0 * DMODEL + c0];
            float* p1 = &C[(size_t)(r0 + 8) * DMODEL + c0];
            p0[0] = acc[mt][nt][0];  p0[1] = acc[mt][nt][1];
            p1[0] = acc[mt][nt][2];  p1[1] = acc[mt][nt][3];
        }
    }
}

// ---------------------------------------------------------------------------
// Launch. Inputs: Q, K, V, Wq, Wk, Wv, bq, bk, bv, mask (mask == tril ones).
// ---------------------------------------------------------------------------
extern "C" void kernel_launch(void* const* d_in, const int* in_sizes, int n_in,
                              void* d_out, int out_size)
{
    const float* Q  = (const float*)d_in[0];
    const float* K  = (const float*)d_in[1];
    const float* V  = (const float*)d_in[2];
    const float* Wq = (const float*)d_in[3];
    const float* Wk = (const float*)d_in[4];
    const float* Wv = (const float*)d_in[5];
    const float* bq = (const float*)d_in[6];
    const float* bk = (const float*)d_in[7];
    const float* bv = (const float*)d_in[8];
    float* Out = (float*)d_out;

    // Opt-in to >48KB dynamic smem. Idempotent; harmless if it errors during
    // graph capture (already set by the correctness call in the same process).
    cudaFuncSetAttribute(proj_kernel,   cudaFuncAttributeMaxDynamicSharedMemorySize, SMEM_PROJ_BYTES);
    cudaFuncSetAttribute(scores_kernel, cudaFuncAttributeMaxDynamicSharedMemorySize, SMEM_SCOR_BYTES);
    cudaFuncSetAttribute(out_kernel,    cudaFuncAttributeMaxDynamicSharedMemorySize, SMEM_PROJ_BYTES);

    proj_kernel<<<dim3(DMODEL / 128, NROWS / 128, 3), 256, SMEM_PROJ_BYTES>>>(
        Q, K, V, Wq, Wk, Wv, bq, bk, bv);
    scores_kernel<<<dim3(SEQ / 128, SEQ / 128, BATCH), 256, SMEM_SCOR_BYTES>>>();
    softmax_kernel<<<NROWS, 256>>>();
    out_kernel<<<dim3(DMODEL / 128, SEQ / 128, BATCH), 256, SMEM_PROJ_BYTES>>>(Out);
}

// round 5
// speedup vs baseline: 3.6473x; 1.0369x over previous
#include <cuda_runtime.h>
#include <cstdint>

// Problem dims (fixed by the reference)
#define BATCH 8
#define SEQ   2048
#define DMODEL 1024
#define NROWS (BATCH * SEQ)          // 16384

// Scratch: rounded inputs, rounded weights, projections (rounded), scores
__device__ float g_rq[(size_t)NROWS * DMODEL];
__device__ float g_rk[(size_t)NROWS * DMODEL];
__device__ float g_rv[(size_t)NROWS * DMODEL];
__device__ float g_wr[(size_t)3 * DMODEL * DMODEL];
__device__ float g_proj_q[(size_t)NROWS * DMODEL];
__device__ float g_proj_k[(size_t)NROWS * DMODEL];
__device__ float g_proj_v[(size_t)NROWS * DMODEL];
__device__ float g_scores[(size_t)BATCH * SEQ * SEQ];

// ---------------------------------------------------------------------------
// Helpers
// ---------------------------------------------------------------------------
__device__ __forceinline__ float rna_tf32(float x) {
    uint32_t r; asm("cvt.rna.tf32.f32 %0, %1;" : "=r"(r) : "f"(x));
    return __uint_as_float(r);
}

__device__ __forceinline__ void mma8(float* c,
                                     uint32_t a0, uint32_t a1, uint32_t a2, uint32_t a3,
                                     uint32_t b0, uint32_t b1) {
    asm volatile(
        "mma.sync.aligned.m16n8k8.row.col.f32.tf32.tf32.f32 "
        "{%0,%1,%2,%3},{%4,%5,%6,%7},{%8,%9},{%0,%1,%2,%3};\n"
        : "+f"(c[0]), "+f"(c[1]), "+f"(c[2]), "+f"(c[3])
        : "r"(a0), "r"(a1), "r"(a2), "r"(a3), "r"(b0), "r"(b1));
}

__device__ __forceinline__ void cpa16(uint32_t saddr, const void* g) {
    asm volatile("cp.async.cg.shared.global [%0], [%1], 16;\n" :: "r"(saddr), "l"(g));
}
#define CPA_COMMIT()  asm volatile("cp.async.commit_group;\n")
#define CPA_WAIT1()   asm volatile("cp.async.wait_group 1;\n" ::: "memory")
#define CPA_WAIT0()   asm volatile("cp.async.wait_group 0;\n" ::: "memory")

// SMEM layout (u32 indices), 2 stages each.
// A tile:   [128][36]  (m-major, stride 36)
// B tile:   [32][136]  (k-major, stride 136) for proj/out
// B tile T: [128][36]  (j-major, stride 36)  for scores
#define AS_STRIDE 36
#define AS_U32    (128 * AS_STRIDE)       // 4608
#define BS_STRIDE 136
#define BS_U32    (32 * BS_STRIDE)        // 4352
#define SMEM_PROJ_BYTES ((2 * AS_U32 + 2 * BS_U32) * 4)   // 71680
#define SMEM_SCOR_BYTES ((2 * AS_U32 + 2 * AS_U32) * 4)   // 73728

// ---------------------------------------------------------------------------
// Pre-pass 1: round Q,K,V to tf32-rna once (removes all cvt from mainloops)
// ---------------------------------------------------------------------------
__global__ __launch_bounds__(256) void round_qkv(
    const float* __restrict__ Q, const float* __restrict__ K, const float* __restrict__ V)
{
    const size_t n4 = (size_t)NROWS * DMODEL / 4;
    for (size_t i = (size_t)blockIdx.x * blockDim.x + threadIdx.x; i < n4;
         i += (size_t)gridDim.x * blockDim.x) {
        float4 a;
        a = ((const float4*)Q)[i];
        ((float4*)g_rq)[i] = make_float4(rna_tf32(a.x), rna_tf32(a.y), rna_tf32(a.z), rna_tf32(a.w));
        a = ((const float4*)K)[i];
        ((float4*)g_rk)[i] = make_float4(rna_tf32(a.x), rna_tf32(a.y), rna_tf32(a.z), rna_tf32(a.w));
        a = ((const float4*)V)[i];
        ((float4*)g_rv)[i] = make_float4(rna_tf32(a.x), rna_tf32(a.y), rna_tf32(a.z), rna_tf32(a.w));
    }
}

// Pre-pass 2: round W (elementwise; layout unchanged)
__global__ __launch_bounds__(256) void round_w(
    const float* __restrict__ Wq, const float* __restrict__ Wk, const float* __restrict__ Wv)
{
    const size_t n4 = (size_t)DMODEL * DMODEL / 4;
    const size_t stride = (size_t)gridDim.x * blockDim.x;
    for (size_t i = (size_t)blockIdx.x * blockDim.x + threadIdx.x; i < n4; i += stride) {
        float4 a;
        a = ((const float4*)Wq)[i];
        ((float4*)g_wr)[i] = make_float4(rna_tf32(a.x), rna_tf32(a.y), rna_tf32(a.z), rna_tf32(a.w));
        a = ((const float4*)Wk)[i];
        ((float4*)(g_wr + (size_t)DMODEL * DMODEL))[i] =
            make_float4(rna_tf32(a.x), rna_tf32(a.y), rna_tf32(a.z), rna_tf32(a.w));
        a = ((const float4*)Wv)[i];
        ((float4*)(g_wr + (size_t)2 * DMODEL * DMODEL))[i] =
            make_float4(rna_tf32(a.x), rna_tf32(a.y), rna_tf32(a.z), rna_tf32(a.w));
    }
}

// ---------------------------------------------------------------------------
// Kernel 1: projections. C[n,e] = round( sum_d A[n,d]*W[d,e] + b[e] )
// grid = (DMODEL/128, NROWS/128, 3)
// ---------------------------------------------------------------------------
__global__ __launch_bounds__(256, 2) void proj_kernel(
    const float* __restrict__ bq, const float* __restrict__ bk, const float* __restrict__ bv)
{
    const int which = blockIdx.z;
    const float* A    = (which == 0) ? g_rq : (which == 1) ? g_rk : g_rv;
    const float* W    = g_wr + (size_t)which * DMODEL * DMODEL;
    const float* bias = (which == 0) ? bq : (which == 1) ? bk : bv;
    float* C          = (which == 0) ? g_proj_q : (which == 1) ? g_proj_k : g_proj_v;

    extern __shared__ uint32_t sm[];
    const uint32_t smb = (uint32_t)__cvta_generic_to_shared(sm);

    const int m0 = blockIdx.y * 128;
    const int n0 = blockIdx.x * 128;
    const int t  = threadIdx.x;
    const int warp = t >> 5, lane = t & 31;
    const int wm = warp >> 2, wn = warp & 3;
    const int g  = lane >> 2, tq = lane & 3;

    const int a_row = t >> 1,  a_c4 = (t & 1)  * 4;  // unused pattern replaced below
    (void)a_row; (void)a_c4;
    const int ar = t >> 3, ac4 = (t & 7) * 4;        // 32 rows/chunk over 8 k... no:
    (void)ar; (void)ac4;

    // cp.async addressing: A tile 128 rows x 8 k (2 chunks/row-pair layout)
    const int arow = t >> 1, ak4 = (t & 1) * 4;
    const int brow = t >> 5, bn4 = (t & 31) * 4;

    float acc[4][4][4];
    #pragma unroll
    for (int i = 0; i < 4; i++)
        #pragma unroll
        for (int j = 0; j < 4; j++)
            #pragma unroll
            for (int c = 0; c < 4; c++) acc[i][j][c] = 0.f;

    const int T = DMODEL / 32;

    auto issue = [&](int tt, int s) {
        const int k0 = tt * 32;
        // A: 128 rows x 32 k = 4096 u32 = 1024 chunks; 256 thr x 4
        #pragma unroll
        for (int i = 0; i < 4; i++) {
            const int ch = t + i * 256;
            const int r = ch >> 3, c4 = (ch & 7) * 4;
            cpa16(smb + (s * AS_U32 + r * AS_STRIDE + c4) * 4,
                  &A[(size_t)(m0 + r) * DMODEL + k0 + c4]);
        }
        // B: 32 k-rows x 128 n = 1024 chunks
        #pragma unroll
        for (int i = 0; i < 4; i++) {
            const int ch = t + i * 256;
            const int r = ch >> 5, c4 = (ch & 31) * 4;
            cpa16(smb + (2 * AS_U32 + s * BS_U32 + r * BS_STRIDE + c4) * 4,
                  &W[(size_t)(k0 + r) * DMODEL + n0 + c4]);
        }
    };
    (void)arow; (void)ak4; (void)brow; (void)bn4;

    issue(0, 0);
    CPA_COMMIT();

    for (int tt = 0; tt < T; tt++) {
        const int cur = tt & 1;
        if (tt + 1 < T) { issue(tt + 1, cur ^ 1); CPA_COMMIT(); CPA_WAIT1(); }
        else           { CPA_WAIT0(); }
        __syncthreads();

        const uint32_t* As = sm + cur * AS_U32;
        const uint32_t* Bs = sm + 2 * AS_U32 + cur * BS_U32;

        #pragma unroll
        for (int ks = 0; ks < 4; ks++) {
            const int kb = ks * 8;
            uint32_t af[4][4], bf[4][2];
            #pragma unroll
            for (int mt = 0; mt < 4; mt++) {
                const int r0 = wm * 64 + mt * 16 + g;
                af[mt][0] = As[(r0)     * AS_STRIDE + kb + tq];
                af[mt][1] = As[(r0 + 8) * AS_STRIDE + kb + tq];
                af[mt][2] = As[(r0)     * AS_STRIDE + kb + tq + 4];
                af[mt][3] = As[(r0 + 8) * AS_STRIDE + kb + tq + 4];
            }
            #pragma unroll
            for (int nt = 0; nt < 4; nt++) {
                const int c0 = wn * 32 + nt * 8 + g;
                bf[nt][0] = Bs[(kb + tq)     * BS_STRIDE + c0];
                bf[nt][1] = Bs[(kb + tq + 4) * BS_STRIDE + c0];
            }
            #pragma unroll
            for (int mt = 0; mt < 4; mt++)
                #pragma unroll
                for (int nt = 0; nt < 4; nt++)
                    mma8(acc[mt][nt], af[mt][0], af[mt][1], af[mt][2], af[mt][3],
                         bf[nt][0], bf[nt][1]);
        }
        __syncthreads();
    }

    // Epilogue: C = round(acc + bias)  (pre-rounded for downstream GEMMs)
    #pragma unroll
    for (int mt = 0; mt < 4; mt++) {
        const int r0 = m0 + wm * 64 + mt * 16 + g;
        #pragma unroll
        for (int nt = 0; nt < 4; nt++) {
            const int c0 = n0 + wn * 32 + nt * 8 + tq * 2;
            const float b0 = bias[c0], b1 = bias[c0 + 1];
            float* p0 = &C[(size_t)r0 * DMODEL + c0];
            float* p1 = &C[(size_t)(r0 + 8) * DMODEL + c0];
            p0[0] = rna_tf32(acc[mt][nt][0] + b0);  p0[1] = rna_tf32(acc[mt][nt][1] + b1);
            p1[0] = rna_tf32(acc[mt][nt][2] + b0);  p1[1] = rna_tf32(acc[mt][nt][3] + b1);
        }
    }
}

// ---------------------------------------------------------------------------
// Kernel 2: scores[b,i,j] = q[b,i,:]·k[b,j,:]/32 on lower-triangle tiles.
// No masking writes: softmax masks by index. grid = (SEQ/128, SEQ/128, BATCH)
// ---------------------------------------------------------------------------
__global__ __launch_bounds__(256, 2) void scores_kernel()
{
    const int jt = blockIdx.x, it = blockIdx.y, b = blockIdx.z;
    if (jt > it) return;

    const float* q = g_proj_q + (size_t)b * SEQ * DMODEL;
    const float* k = g_proj_k + (size_t)b * SEQ * DMODEL;
    float* sc      = g_scores + (size_t)b * SEQ * SEQ;

    extern __shared__ uint32_t sm[];
    const uint32_t smb = (uint32_t)__cvta_generic_to_shared(sm);

    const int i0 = it * 128, j0 = jt * 128;
    const int t  = threadIdx.x;
    const int warp = t >> 5, lane = t & 31;
    const int wm = warp >> 2, wn = warp & 3;
    const int g  = lane >> 2, tq = lane & 3;

    float acc[4][4][4];
    #pragma unroll
    for (int i = 0; i < 4; i++)
        #pragma unroll
        for (int j = 0; j < 4; j++)
            #pragma unroll
            for (int c = 0; c < 4; c++) acc[i][j][c] = 0.f;

    const int T = DMODEL / 32;

    auto issue = [&](int tt, int s) {
        const int k0 = tt * 32;
        #pragma unroll
        for (int i = 0; i < 4; i++) {
            const int ch = t + i * 256;
            const int r = ch >> 3, c4 = (ch & 7) * 4;
            cpa16(smb + (s * AS_U32 + r * AS_STRIDE + c4) * 4,
                  &q[(size_t)(i0 + r) * DMODEL + k0 + c4]);
            cpa16(smb + ((2 + s) * AS_U32 + r * AS_STRIDE + c4) * 4,
                  &k[(size_t)(j0 + r) * DMODEL + k0 + c4]);
        }
    };

    issue(0, 0);
    CPA_COMMIT();

    for (int tt = 0; tt < T; tt++) {
        const int cur = tt & 1;
        if (tt + 1 < T) { issue(tt + 1, cur ^ 1); CPA_COMMIT(); CPA_WAIT1(); }
        else           { CPA_WAIT0(); }
        __syncthreads();

        const uint32_t* As = sm + cur * AS_U32;
        const uint32_t* Bs = sm + (2 + cur) * AS_U32;

        #pragma unroll
        for (int ks = 0; ks < 4; ks++) {
            const int kb = ks * 8;
            uint32_t af[4][4], bf[4][2];
            #pragma unroll
            for (int mt = 0; mt < 4; mt++) {
                const int r0 = wm * 64 + mt * 16 + g;
                af[mt][0] = As[(r0)     * AS_STRIDE + kb + tq];
                af[mt][1] = As[(r0 + 8) * AS_STRIDE + kb + tq];
                af[mt][2] = As[(r0)     * AS_STRIDE + kb + tq + 4];
                af[mt][3] = As[(r0 + 8) * AS_STRIDE + kb + tq + 4];
            }
            #pragma unroll
            for (int nt = 0; nt < 4; nt++) {
                const int c0 = wn * 32 + nt * 8 + g;
                bf[nt][0] = Bs[c0 * AS_STRIDE + kb + tq];
                bf[nt][1] = Bs[c0 * AS_STRIDE + kb + tq + 4];
            }
            #pragma unroll
            for (int mt = 0; mt < 4; mt++)
                #pragma unroll
                for (int nt = 0; nt < 4; nt++)
                    mma8(acc[mt][nt], af[mt][0], af[mt][1], af[mt][2], af[mt][3],
                         bf[nt][0], bf[nt][1]);
        }
        __syncthreads();
    }

    const float scale = 0.03125f;   // 1/sqrt(1024)
    #pragma unroll
    for (int mt = 0; mt < 4; mt++) {
        const int gi0 = i0 + wm * 64 + mt * 16 + g;
        #pragma unroll
        for (int nt = 0; nt < 4; nt++) {
            const int gj = j0 + wn * 32 + nt * 8 + tq * 2;
            float* p0 = &sc[(size_t)gi0 * SEQ + gj];
            float* p1 = &sc[(size_t)(gi0 + 8) * SEQ + gj];
            p0[0] = acc[mt][nt][0] * scale;  p0[1] = acc[mt][nt][1] * scale;
            p1[0] = acc[mt][nt][2] * scale;  p1[1] = acc[mt][nt][3] * scale;
        }
    }
}

// ---------------------------------------------------------------------------
// Kernel 3: causal softmax, single global read (register-cached float4),
// masks by index, writes rounded P for j<len, zeros for [len, ceil128(len)).
// ---------------------------------------------------------------------------
__global__ __launch_bounds__(256) void softmax_kernel()
{
    const int r = blockIdx.x;
    const int b = r >> 11, i = r & 2047;
    float* row = g_scores + (size_t)b * SEQ * SEQ + (size_t)i * SEQ;
    const int len = i + 1;
    const int kmax = ((i >> 7) + 1) << 7;
    const int n4 = kmax >> 2;
    const int t = threadIdx.x;

    __shared__ float red[256];

    float4 v[2];
    float mx = -3.0e38f;
    #pragma unroll
    for (int kk = 0; kk < 2; kk++) {
        const int i4 = t + kk * 256;
        if (i4 < n4) {
            v[kk] = ((const float4*)row)[i4];
            const int j = i4 * 4;
            if (j + 0 < len) mx = fmaxf(mx, v[kk].x);
            if (j + 1 < len) mx = fmaxf(mx, v[kk].y);
            if (j + 2 < len) mx = fmaxf(mx, v[kk].z);
            if (j + 3 < len) mx = fmaxf(mx, v[kk].w);
        }
    }
    red[t] = mx;
    __syncthreads();
    for (int s2 = 128; s2 > 0; s2 >>= 1) {
        if (t < s2) red[t] = fmaxf(red[t], red[t + s2]);
        __syncthreads();
    }
    mx = red[0];
    __syncthreads();

    float sum = 0.f;
    #pragma unroll
    for (int kk = 0; kk < 2; kk++) {
        const int i4 = t + kk * 256;
        if (i4 < n4) {
            const int j = i4 * 4;
            v[kk].x = (j + 0 < len) ? __expf(v[kk].x - mx) : 0.f;
            v[kk].y = (j + 1 < len) ? __expf(v[kk].y - mx) : 0.f;
            v[kk].z = (j + 2 < len) ? __expf(v[kk].z - mx) : 0.f;
            v[kk].w = (j + 3 < len) ? __expf(v[kk].w - mx) : 0.f;
            sum += v[kk].x + v[kk].y + v[kk].z + v[kk].w;
        }
    }
    red[t] = sum;
    __syncthreads();
    for (int s2 = 128; s2 > 0; s2 >>= 1) {
        if (t < s2) red[t] += red[t + s2];
        __syncthreads();
    }
    const float inv = 1.0f / red[0];

    #pragma unroll
    for (int kk = 0; kk < 2; kk++) {
        const int i4 = t + kk * 256;
        if (i4 < n4) {
            float4 o;
            o.x = rna_tf32(v[kk].x * inv);
            o.y = rna_tf32(v[kk].y * inv);
            o.z = rna_tf32(v[kk].z * inv);
            o.w = rna_tf32(v[kk].w * inv);
            ((float4*)row)[i4] = o;
        }
    }
}

// ---------------------------------------------------------------------------
// Kernel 4: out = P · v  (NN GEMM, K truncated at causal boundary)
// grid = (DMODEL/128, SEQ/128, BATCH)
// ---------------------------------------------------------------------------
__global__ __launch_bounds__(256, 2) void out_kernel(float* __restrict__ Out)
{
    const int b  = blockIdx.z;
    const int it = blockIdx.y;
    const int nt0 = blockIdx.x;

    const float* Wt = g_scores + (size_t)b * SEQ * SEQ;
    const float* Vv = g_proj_v + (size_t)b * SEQ * DMODEL;
    float* C        = Out + (size_t)b * SEQ * DMODEL;

    extern __shared__ uint32_t sm[];
    const uint32_t smb = (uint32_t)__cvta_generic_to_shared(sm);

    const int m0 = it * 128;
    const int n0 = nt0 * 128;
    const int t  = threadIdx.x;
    const int warp = t >> 5, lane = t & 31;
    const int wm = warp >> 2, wn = warp & 3;
    const int g  = lane >> 2, tq = lane & 3;

    float acc[4][4][4];
    #pragma unroll
    for (int i = 0; i < 4; i++)
        #pragma unroll
        for (int j = 0; j < 4; j++)
            #pragma unroll
            for (int c = 0; c < 4; c++) acc[i][j][c] = 0.f;

    const int T = (it + 1) * 4;

    auto issue = [&](int tt, int s) {
        const int k0 = tt * 32;
        #pragma unroll
        for (int i = 0; i < 4; i++) {
            const int ch = t + i * 256;
            const int r = ch >> 3, c4 = (ch & 7) * 4;
            cpa16(smb + (s * AS_U32 + r * AS_STRIDE + c4) * 4,
                  &Wt[(size_t)(m0 + r) * SEQ + k0 + c4]);
        }
        #pragma unroll
        for (int i = 0; i < 4; i++) {
            const int ch = t + i * 256;
            const int r = ch >> 5, c4 = (ch & 31) * 4;
            cpa16(smb + (2 * AS_U32 + s * BS_U32 + r * BS_STRIDE + c4) * 4,
                  &Vv[(size_t)(k0 + r) * DMODEL + n0 + c4]);
        }
    };

    issue(0, 0);
    CPA_COMMIT();

    for (int tt = 0; tt < T; tt++) {
        const int cur = tt & 1;
        if (tt + 1 < T) { issue(tt + 1, cur ^ 1); CPA_COMMIT(); CPA_WAIT1(); }
        else           { CPA_WAIT0(); }
        __syncthreads();

        const uint32_t* As = sm + cur * AS_U32;
        const uint32_t* Bs = sm + 2 * AS_U32 + cur * BS_U32;

        #pragma unroll
        for (int ks = 0; ks < 4; ks++) {
            const int kb = ks * 8;
            uint32_t af[4][4], bf[4][2];
            #pragma unroll
            for (int mt = 0; mt < 4; mt++) {
                const int r0 = wm * 64 + mt * 16 + g;
                af[mt][0] = As[(r0)     * AS_STRIDE + kb + tq];
                af[mt][1] = As[(r0 + 8) * AS_STRIDE + kb + tq];
                af[mt][2] = As[(r0)     * AS_STRIDE + kb + tq + 4];
                af[mt][3] = As[(r0 + 8) * AS_STRIDE + kb + tq + 4];
            }
            #pragma unroll
            for (int nt = 0; nt < 4; nt++) {
                const int c0 = wn * 32 + nt * 8 + g;
                bf[nt][0] = Bs[(kb + tq)     * BS_STRIDE + c0];
                bf[nt][1] = Bs[(kb + tq + 4) * BS_STRIDE + c0];
            }
            #pragma unroll
            for (int mt = 0; mt < 4; mt++)
                #pragma unroll
                for (int nt = 0; nt < 4; nt++)
                    mma8(acc[mt][nt], af[mt][0], af[mt][1], af[mt][2], af[mt][3],
                         bf[nt][0], bf[nt][1]);
        }
        __syncthreads();
    }

    #pragma unroll
    for (int mt = 0; mt < 4; mt++) {
        const int r0 = m0 + wm * 64 + mt * 16 + g;
        #pragma unroll
        for (int nt = 0; nt < 4; nt++) {
            const int c0 = n0 + wn * 32 + nt * 8 + tq * 2;
            float* p0 = &C[(size_t)r0 * DMODEL + c0];
            float* p1 = &C[(size_t)(r0 + 8) * DMODEL + c0];
            p0[0] = acc[mt][nt][0];  p0[1] = acc[mt][nt][1];
            p1[0] = acc[mt][nt][2];  p1[1] = acc[mt][nt][3];
        }
    }
}

// ---------------------------------------------------------------------------
// Launch. Inputs: Q, K, V, Wq, Wk, Wv, bq, bk, bv, mask (mask == tril ones).
// ---------------------------------------------------------------------------
extern "C" void kernel_launch(void* const* d_in, const int* in_sizes, int n_in,
                              void* d_out, int out_size)
{
    const float* Q  = (const float*)d_in[0];
    const float* K  = (const float*)d_in[1];
    const float* V  = (const float*)d_in[2];
    const float* Wq = (const float*)d_in[3];
    const float* Wk = (const float*)d_in[4];
    const float* Wv = (const float*)d_in[5];
    const float* bq = (const float*)d_in[6];
    const float* bk = (const float*)d_in[7];
    const float* bv = (const float*)d_in[8];
    float* Out = (float*)d_out;

    cudaFuncSetAttribute(proj_kernel,   cudaFuncAttributeMaxDynamicSharedMemorySize, SMEM_PROJ_BYTES);
    cudaFuncSetAttribute(scores_kernel, cudaFuncAttributeMaxDynamicSharedMemorySize, SMEM_SCOR_BYTES);
    cudaFuncSetAttribute(out_kernel,    cudaFuncAttributeMaxDynamicSharedMemorySize, SMEM_PROJ_BYTES);

    round_qkv<<<2048, 256>>>(Q, K, V);
    round_w<<<512, 256>>>(Wq, Wk, Wv);
    proj_kernel<<<dim3(DMODEL / 128, NROWS / 128, 3), 256, SMEM_PROJ_BYTES>>>(bq, bk, bv);
    scores_kernel<<<dim3(SEQ / 128, SEQ / 128, BATCH), 256, SMEM_SCOR_BYTES>>>();
    softmax_kernel<<<NROWS, 256>>>();
    out_kernel<<<dim3(DMODEL / 128, SEQ / 128, BATCH), 256, SMEM_PROJ_BYTES>>>(Out);
}